// round 1
// baseline (speedup 1.0000x reference)
#include <cuda_runtime.h>
#include <cstdint>
#include <cstddef>

#define N_CTX 4096
#define D_MODEL 2048

// Scratch (no cudaMalloc allowed): X = E@qk, S = scores/probs, Y = P@E
__device__ float g_X[(size_t)N_CTX * D_MODEL];
__device__ float g_S[(size_t)N_CTX * N_CTX];
__device__ float g_Y[(size_t)N_CTX * D_MODEL];

// ---------------------------------------------------------------------------
// Generic fp32 SGEMM: C[M,N] = A[M,K] * op(B)
//   B_TRANS  : B is [N,K] row-major, use B^T   (scores = X @ E^T)
//   CAUSAL_OUT: zero elements with col > row; skip blocks fully above diagonal
//   CAUSAL_K : only accumulate k-tiles with k <= rowBase+BM-1 (P upper == 0)
// Tile 128x128x16, 256 threads, 8x8 per-thread microtile, register prefetch.
// All dims are multiples of the tile sizes (4096 / 2048), no bounds checks.
// ---------------------------------------------------------------------------
template<bool B_TRANS, bool CAUSAL_OUT, bool CAUSAL_K>
__global__ void __launch_bounds__(256, 2)
sgemm128(const float* __restrict__ A, const float* __restrict__ B,
         float* __restrict__ C, int M, int N, int K)
{
    constexpr int BM = 128, BN = 128, BK = 16;
    __shared__ float As[BK][BM];
    __shared__ float Bs[BK][BN];

    const int rowBase = blockIdx.y * BM;
    const int colBase = blockIdx.x * BN;
    const int tid = threadIdx.x;

    if (CAUSAL_OUT && colBase > rowBase + BM - 1) {
        // Fully above the diagonal: write zeros (P must be 0 there for K4).
        const float4 z = make_float4(0.f, 0.f, 0.f, 0.f);
        for (int i = tid; i < BM * BN / 4; i += 256) {
            int r = i >> 5;              // /32 float4 per row
            int c = (i & 31) << 2;
            *reinterpret_cast<float4*>(&C[(size_t)(rowBase + r) * N + colBase + c]) = z;
        }
        return;
    }

    const int numTiles = CAUSAL_K ? (rowBase + BM) / BK : (K / BK);

    // --- load-index setup ---------------------------------------------------
    // A tile: 128 rows x 16 cols = 512 float4 (4 per row), 2 per thread.
    const int ldr = tid >> 2;            // 0..63
    const int ldc = (tid & 3) << 2;      // 0,4,8,12
    // B (NN) tile: 16 rows x 128 cols = 512 float4 (32 per row), 2 per thread.
    const int bnr = tid >> 5;            // 0..7
    const int bnc = (tid & 31) << 2;     // 0..124

    float4 a0g, a1g, b0g, b1g;

    auto loadTile = [&](int kBase) {
        a0g = *reinterpret_cast<const float4*>(&A[(size_t)(rowBase + ldr)      * K + kBase + ldc]);
        a1g = *reinterpret_cast<const float4*>(&A[(size_t)(rowBase + ldr + 64) * K + kBase + ldc]);
        if (B_TRANS) {
            b0g = *reinterpret_cast<const float4*>(&B[(size_t)(colBase + ldr)      * K + kBase + ldc]);
            b1g = *reinterpret_cast<const float4*>(&B[(size_t)(colBase + ldr + 64) * K + kBase + ldc]);
        } else {
            b0g = *reinterpret_cast<const float4*>(&B[(size_t)(kBase + bnr)     * N + colBase + bnc]);
            b1g = *reinterpret_cast<const float4*>(&B[(size_t)(kBase + bnr + 8) * N + colBase + bnc]);
        }
    };

    auto storeTile = [&]() {
        As[ldc + 0][ldr] = a0g.x;  As[ldc + 1][ldr] = a0g.y;
        As[ldc + 2][ldr] = a0g.z;  As[ldc + 3][ldr] = a0g.w;
        As[ldc + 0][ldr + 64] = a1g.x;  As[ldc + 1][ldr + 64] = a1g.y;
        As[ldc + 2][ldr + 64] = a1g.z;  As[ldc + 3][ldr + 64] = a1g.w;
        if (B_TRANS) {
            Bs[ldc + 0][ldr] = b0g.x;  Bs[ldc + 1][ldr] = b0g.y;
            Bs[ldc + 2][ldr] = b0g.z;  Bs[ldc + 3][ldr] = b0g.w;
            Bs[ldc + 0][ldr + 64] = b1g.x;  Bs[ldc + 1][ldr + 64] = b1g.y;
            Bs[ldc + 2][ldr + 64] = b1g.z;  Bs[ldc + 3][ldr + 64] = b1g.w;
        } else {
            *reinterpret_cast<float4*>(&Bs[bnr][bnc])     = b0g;
            *reinterpret_cast<float4*>(&Bs[bnr + 8][bnc]) = b1g;
        }
    };

    // --- main loop ----------------------------------------------------------
    const int tm = (tid >> 4) << 3;      // 0..120 step 8
    const int tn = (tid & 15) << 3;

    float acc[8][8];
    #pragma unroll
    for (int i = 0; i < 8; ++i)
        #pragma unroll
        for (int j = 0; j < 8; ++j) acc[i][j] = 0.f;

    loadTile(0);
    for (int t = 0; t < numTiles; ++t) {
        storeTile();
        __syncthreads();
        if (t + 1 < numTiles) loadTile((t + 1) * BK);

        #pragma unroll
        for (int kk = 0; kk < BK; ++kk) {
            float4 av0 = *reinterpret_cast<const float4*>(&As[kk][tm]);
            float4 av1 = *reinterpret_cast<const float4*>(&As[kk][tm + 4]);
            float4 bv0 = *reinterpret_cast<const float4*>(&Bs[kk][tn]);
            float4 bv1 = *reinterpret_cast<const float4*>(&Bs[kk][tn + 4]);
            float a[8] = {av0.x, av0.y, av0.z, av0.w, av1.x, av1.y, av1.z, av1.w};
            float b[8] = {bv0.x, bv0.y, bv0.z, bv0.w, bv1.x, bv1.y, bv1.z, bv1.w};
            #pragma unroll
            for (int i = 0; i < 8; ++i)
                #pragma unroll
                for (int j = 0; j < 8; ++j)
                    acc[i][j] = fmaf(a[i], b[j], acc[i][j]);
        }
        __syncthreads();
    }

    // --- epilogue -----------------------------------------------------------
    #pragma unroll
    for (int i = 0; i < 8; ++i) {
        const int gr = rowBase + tm + i;
        #pragma unroll
        for (int j4 = 0; j4 < 2; ++j4) {
            float4 v = make_float4(acc[i][j4 * 4 + 0], acc[i][j4 * 4 + 1],
                                   acc[i][j4 * 4 + 2], acc[i][j4 * 4 + 3]);
            if (CAUSAL_OUT) {
                const int gc = colBase + tn + j4 * 4;
                if (gc + 0 > gr) v.x = 0.f;
                if (gc + 1 > gr) v.y = 0.f;
                if (gc + 2 > gr) v.z = 0.f;
                if (gc + 3 > gr) v.w = 0.f;
            }
            *reinterpret_cast<float4*>(&C[(size_t)gr * N + colBase + tn + j4 * 4]) = v;
        }
    }
}

// ---------------------------------------------------------------------------
// In-place causal row softmax: row i uses columns [0, i]; columns > i stay 0.
// ---------------------------------------------------------------------------
__global__ void __launch_bounds__(256)
softmax_rows(float* __restrict__ S)
{
    __shared__ float red[256];
    const int i = blockIdx.x;
    const int len = i + 1;
    float* row = S + (size_t)i * N_CTX;
    const int tid = threadIdx.x;

    float m = -1e30f;
    for (int j = tid; j < len; j += 256) m = fmaxf(m, row[j]);
    red[tid] = m;
    __syncthreads();
    #pragma unroll
    for (int s = 128; s > 0; s >>= 1) {
        if (tid < s) red[tid] = fmaxf(red[tid], red[tid + s]);
        __syncthreads();
    }
    m = red[0];
    __syncthreads();

    float sum = 0.f;
    for (int j = tid; j < len; j += 256) sum += __expf(row[j] - m);
    red[tid] = sum;
    __syncthreads();
    #pragma unroll
    for (int s = 128; s > 0; s >>= 1) {
        if (tid < s) red[tid] += red[tid + s];
        __syncthreads();
    }
    const float inv = 1.0f / red[0];

    for (int j = tid; j < len; j += 256) row[j] = __expf(row[j] - m) * inv;
}

// ---------------------------------------------------------------------------
extern "C" void kernel_launch(void* const* d_in, const int* in_sizes, int n_in,
                              void* d_out, int out_size)
{
    const float* E  = (const float*)d_in[0];   // [4096, 2048]
    const float* qk = (const float*)d_in[1];   // [2048, 2048]
    const float* ov = (const float*)d_in[2];   // [2048, 2048]
    float* out = (float*)d_out;                // [4096, 2048]

    void *pX, *pS, *pY;
    cudaGetSymbolAddress(&pX, g_X);
    cudaGetSymbolAddress(&pS, g_S);
    cudaGetSymbolAddress(&pY, g_Y);
    float* X = (float*)pX;
    float* S = (float*)pS;
    float* Y = (float*)pY;

    dim3 blk(256);

    // K1: X = E @ qk                     [4096,2048] = [4096,2048]x[2048,2048]
    sgemm128<false, false, false><<<dim3(D_MODEL / 128, N_CTX / 128), blk>>>(
        E, qk, X, N_CTX, D_MODEL, D_MODEL);

    // K2: S = X @ E^T, causal-masked     [4096,4096]
    sgemm128<true, true, false><<<dim3(N_CTX / 128, N_CTX / 128), blk>>>(
        X, E, S, N_CTX, N_CTX, D_MODEL);

    // K3: in-place causal softmax per row
    softmax_rows<<<N_CTX, blk>>>(S);

    // K4: Y = P @ E (k-tiles limited to <= row block end; P upper is 0)
    sgemm128<false, false, true><<<dim3(D_MODEL / 128, N_CTX / 128), blk>>>(
        S, E, Y, N_CTX, D_MODEL, N_CTX);

    // K5: out = Y @ ov
    sgemm128<false, false, false><<<dim3(D_MODEL / 128, N_CTX / 128), blk>>>(
        Y, ov, out, N_CTX, D_MODEL, D_MODEL);
}